// round 15
// baseline (speedup 1.0000x reference)
#include <cuda_runtime.h>
#include <cuda_bf16.h>
#include <cuda_fp16.h>
#include <math.h>

#define N_NODES 50000
#define HID     256
#define NQKV    1024
#define E_EDGES 800000
#define SCAN_B  1024
#define NBLK    ((N_NODES + SCAN_B - 1) / SCAN_B)   // 49

// ---------------- device scratch (no runtime allocation allowed) ----------------
__device__ __align__(16) float  g_qs[N_NODES * 512];        // q(0:256) | skip(256:512), fp32
__device__ __align__(16) __nv_bfloat16 g_k[N_NODES * 256];
__device__ __align__(16) __nv_bfloat16 g_v[N_NODES * 256];
__device__ __align__(16) __half g_x16[N_NODES * 256];       // fp16 copy of X, 25.6 MB
__device__ __align__(16) uint2  g_Wfrag16[128 * 16 * 32];   // fp16 B-fragments (m16n8k16), 512 KB
__device__ float g_bcat[NQKV];
__device__ int   g_deg[N_NODES];
__device__ int   g_off[N_NODES];
__device__ int   g_cur[N_NODES];
__device__ int   g_srcSorted[E_EDGES];
__device__ int   g_bsum[NBLK];

// ---------------- helpers ----------------
__device__ __forceinline__ void mma_f16(float* d, const unsigned* a, const unsigned* b,
                                        const float* c) {
    asm volatile(
        "mma.sync.aligned.m16n8k16.row.col.f32.f16.f16.f32 "
        "{%0,%1,%2,%3}, {%4,%5,%6,%7}, {%8,%9}, {%10,%11,%12,%13};\n"
        : "=f"(d[0]), "=f"(d[1]), "=f"(d[2]), "=f"(d[3])
        : "r"(a[0]), "r"(a[1]), "r"(a[2]), "r"(a[3]),
          "r"(b[0]), "r"(b[1]),
          "f"(c[0]), "f"(c[1]), "f"(c[2]), "f"(c[3]));
}

__device__ __forceinline__ void ldsm_x4(unsigned& r0, unsigned& r1, unsigned& r2,
                                        unsigned& r3, unsigned addr) {
    asm volatile("ldmatrix.sync.aligned.m8n8.x4.shared.b16 {%0,%1,%2,%3}, [%4];"
                 : "=r"(r0), "=r"(r1), "=r"(r2), "=r"(r3) : "r"(addr));
}

__device__ __forceinline__ unsigned smem_u32(const void* p) {
    return (unsigned)__cvta_generic_to_shared(p);
}

__device__ __forceinline__ void cp_async16(unsigned dst, const void* src, int src_bytes) {
    asm volatile("cp.async.cg.shared.global [%0], [%1], 16, %2;"
                 :: "r"(dst), "l"(src), "r"(src_bytes));
}

// ---------------- pack weights into fp16 m16n8k16 B-fragment order (+bias) ------
__global__ void k_packW(const float* __restrict__ Wq, const float* __restrict__ Wk,
                        const float* __restrict__ Wv, const float* __restrict__ Ws,
                        const float* __restrict__ bq, const float* __restrict__ bk,
                        const float* __restrict__ bv, const float* __restrict__ bs) {
    int t = blockIdx.x * blockDim.x + threadIdx.x;
    if (t < 128 * 16 * 32) {
        int lane = t & 31;
        int kb   = (t >> 5) & 15;
        int nb   = t >> 9;
        int n_glob = nb * 8 + (lane >> 2);
        int k0     = kb * 16 + (lane & 3) * 2;
        int seg  = n_glob >> 8;
        int ncol = n_glob & 255;
        const float* W = (seg == 0) ? Wq : (seg == 1) ? Wk : (seg == 2) ? Wv : Ws;
        __half2 h0 = __floats2half2_rn(W[k0 * HID + ncol],       W[(k0 + 1) * HID + ncol]);
        __half2 h1 = __floats2half2_rn(W[(k0 + 8) * HID + ncol], W[(k0 + 9) * HID + ncol]);
        uint2 u;
        u.x = *reinterpret_cast<unsigned*>(&h0);
        u.y = *reinterpret_cast<unsigned*>(&h1);
        g_Wfrag16[t] = u;
    }
    if (t < NQKV) {
        int seg = t >> 8, idx = t & 255;
        const float* b = (seg == 0) ? bq : (seg == 1) ? bk : (seg == 2) ? bv : bs;
        g_bcat[t] = b[idx];
    }
}

// ---------------- X -> fp16 (side stream, overlaps packW) ----------------
__global__ void k_cvtX(const float* __restrict__ X) {
    int t = blockIdx.x * blockDim.x + threadIdx.x;     // over N*256/8
    if (t >= N_NODES * 32) return;
    const float4* xp = reinterpret_cast<const float4*>(X) + t * 2;
    float4 v0 = __ldg(xp), v1 = __ldg(xp + 1);
    __half2 h0 = __floats2half2_rn(v0.x, v0.y);
    __half2 h1 = __floats2half2_rn(v0.z, v0.w);
    __half2 h2 = __floats2half2_rn(v1.x, v1.y);
    __half2 h3 = __floats2half2_rn(v1.z, v1.w);
    uint4 u;
    u.x = *reinterpret_cast<unsigned*>(&h0);
    u.y = *reinterpret_cast<unsigned*>(&h1);
    u.z = *reinterpret_cast<unsigned*>(&h2);
    u.w = *reinterpret_cast<unsigned*>(&h3);
    reinterpret_cast<uint4*>(g_x16)[t] = u;
}

// ---------------- fp16 tensor-core GEMM, 2-stage cp.async -----------------------
// launch_bounds(256,3): cap regs at ~85 -> 3 CTAs/SM (24 warps) for latency hiding.
#define GBM 128
#define GBN 128
#define GBK 32
#define ASTR 40   // fp16 elements per A row
__global__ __launch_bounds__(256, 3) void k_gemm() {
    __shared__ __align__(16) __half As[2][GBM * ASTR];   // 2 x 10240 B
    __shared__ __align__(16) uint2  Bs[2][1024];         // 2 x 8192 B

    const int bm   = blockIdx.y * GBM;
    const int bn   = blockIdx.x * GBN;
    const int tid  = threadIdx.x;
    const int wid  = tid >> 5;
    const int lane = tid & 31;
    const int warp_m = wid >> 2;
    const int warp_n = wid & 3;
    const int gid = lane >> 2;
    const int tig = lane & 3;
    const int nb0 = bn >> 3;

    auto loadA = [&](int stage, int kbase) {
#pragma unroll
        for (int l = 0; l < 2; l++) {
            int u   = tid + l * 256;
            int row = u >> 2;
            int c8  = (u & 3) * 8;
            int gr  = bm + row;
            cp_async16(smem_u32(&As[stage][row * ASTR + c8]),
                       &g_x16[(size_t)gr * 256 + kbase + c8], gr < N_NODES ? 16 : 0);
        }
    };
    auto loadB = [&](int stage, int kbase) {
        int kb0 = kbase >> 4;
#pragma unroll
        for (int l = 0; l < 2; l++) {
            int u      = tid + l * 256;
            int group  = u >> 4;
            int within = u & 15;
            const char* src = reinterpret_cast<const char*>(g_Wfrag16)
                            + ((size_t)((nb0 + (group >> 1)) * 16 + kb0 + (group & 1)) * 256)
                            + within * 16;
            cp_async16(smem_u32(&Bs[stage][0]) + u * 16, src, 16);
        }
    };

    float acc[4][4][4];
#pragma unroll
    for (int mf = 0; mf < 4; mf++)
#pragma unroll
        for (int nf = 0; nf < 4; nf++)
#pragma unroll
            for (int r = 0; r < 4; r++) acc[mf][nf][r] = 0.f;

    loadA(0, 0);
    loadB(0, 0);
    asm volatile("cp.async.commit_group;");

    const int ltile = lane >> 3;
    const int lrow  = lane & 7;
    const int arow0 = warp_m * 64 + lrow + (ltile & 1) * 8;
    const int acol0 = (ltile >> 1) * 8;

    for (int k0 = 0; k0 < HID; k0 += GBK) {
        const int buf = (k0 >> 5) & 1;
        const bool more = (k0 + GBK) < HID;
        if (more) {
            loadA(buf ^ 1, k0 + GBK);
            loadB(buf ^ 1, k0 + GBK);
            asm volatile("cp.async.commit_group;");
            asm volatile("cp.async.wait_group 1;");
        } else {
            asm volatile("cp.async.wait_group 0;");
        }
        __syncthreads();

        const unsigned abase = smem_u32(&As[buf][0]);
#pragma unroll
        for (int ks = 0; ks < 2; ks++) {
            const int kk = ks * 16;
            unsigned bfr[4][2];
#pragma unroll
            for (int nf = 0; nf < 4; nf++) {
                uint2 w = Bs[buf][((warp_n * 4 + nf) * 2 + ks) * 32 + lane];
                bfr[nf][0] = w.x;
                bfr[nf][1] = w.y;
            }
            unsigned afr[4][4];
#pragma unroll
            for (int mf = 0; mf < 4; mf++)
                ldsm_x4(afr[mf][0], afr[mf][1], afr[mf][2], afr[mf][3],
                        abase + ((arow0 + mf * 16) * ASTR + kk + acol0) * 2);
#pragma unroll
            for (int mf = 0; mf < 4; mf++)
#pragma unroll
                for (int nf = 0; nf < 4; nf++)
                    mma_f16(acc[mf][nf], afr[mf], bfr[nf], acc[mf][nf]);
        }
        __syncthreads();
    }

    const int seg = bn >> 8;
    const int segbase = bn & 255;
#pragma unroll
    for (int mf = 0; mf < 4; mf++) {
#pragma unroll
        for (int nf = 0; nf < 4; nf++) {
            int lcol = warp_n * 32 + nf * 8 + tig * 2;
            int cn   = bn + lcol;
            int scol = segbase + lcol;
            float b0 = g_bcat[cn], b1 = g_bcat[cn + 1];
#pragma unroll
            for (int half = 0; half < 2; half++) {
                int row = bm + warp_m * 64 + mf * 16 + gid + half * 8;
                if (row >= N_NODES) continue;
                float o0 = acc[mf][nf][half * 2 + 0] + b0;
                float o1 = acc[mf][nf][half * 2 + 1] + b1;
                if (seg == 0) {
                    *reinterpret_cast<float2*>(&g_qs[(size_t)row * 512 + scol]) =
                        make_float2(o0, o1);
                } else if (seg == 3) {
                    *reinterpret_cast<float2*>(&g_qs[(size_t)row * 512 + 256 + scol]) =
                        make_float2(o0, o1);
                } else {
                    __nv_bfloat162 h = __float22bfloat162_rn(make_float2(o0, o1));
                    __nv_bfloat16* dst = (seg == 1) ? g_k : g_v;
                    *reinterpret_cast<__nv_bfloat162*>(&dst[(size_t)row * 256 + scol]) = h;
                }
            }
        }
    }
}

// ---------------- CSR build (dst-grouped, runs on side stream) ----------------
__global__ void k_zero() {
    int i = blockIdx.x * blockDim.x + threadIdx.x;
    if (i < N_NODES) g_deg[i] = 0;
}

__global__ void k_count(const int* __restrict__ ei) {
    int e = blockIdx.x * blockDim.x + threadIdx.x;
    if (e < E_EDGES) {
        int dst = ei[E_EDGES + e];
        if ((unsigned)dst < N_NODES) atomicAdd(&g_deg[dst], 1);
    }
}

__global__ __launch_bounds__(SCAN_B) void k_scan1() {
    int b = blockIdx.x, t = threadIdx.x;
    int i = b * SCAN_B + t;
    int v = (i < N_NODES) ? g_deg[i] : 0;
    int lane = t & 31, w = t >> 5;
    int x = v;
#pragma unroll
    for (int o = 1; o < 32; o <<= 1) {
        int y = __shfl_up_sync(0xFFFFFFFFu, x, o);
        if (lane >= o) x += y;
    }
    __shared__ int wsum[32];
    if (lane == 31) wsum[w] = x;
    __syncthreads();
    if (w == 0) {
        int s = wsum[lane];
#pragma unroll
        for (int o = 1; o < 32; o <<= 1) {
            int y = __shfl_up_sync(0xFFFFFFFFu, s, o);
            if (lane >= o) s += y;
        }
        wsum[lane] = s;
    }
    __syncthreads();
    int incl = x + (w > 0 ? wsum[w - 1] : 0);
    if (i < N_NODES) g_off[i] = incl - v;
    if (t == SCAN_B - 1) g_bsum[b] = incl;
}

__global__ void k_scan3() {
    __shared__ int pre;
    int b = blockIdx.x;
    if (threadIdx.x == 0) {
        int gb = (b << 8) / SCAN_B;
        int s = 0;
        for (int t = 0; t < gb; t++) s += g_bsum[t];
        pre = s;
    }
    __syncthreads();
    int i = (b << 8) + threadIdx.x;
    if (i < N_NODES) {
        int o = g_off[i] + pre;
        g_off[i] = o;
        g_cur[i] = o;
    }
}

__global__ void k_scatter(const int* __restrict__ ei) {
    int e = blockIdx.x * blockDim.x + threadIdx.x;
    if (e < E_EDGES) {
        int src = ei[e];
        int dst = ei[E_EDGES + e];
        if ((unsigned)src < N_NODES && (unsigned)dst < N_NODES) {
            int p = atomicAdd(&g_cur[dst], 1);
            if ((unsigned)p < E_EDGES) g_srcSorted[p] = src;
        }
    }
}

// ---------------- fused attention + skip + GELU + residual + LayerNorm ----------------
// WARP-PER-NODE (R10 winner, unchanged; at LTS gather roofline).
__global__ __launch_bounds__(256) void k_attn(const float* __restrict__ x,
                                              const float* __restrict__ gamma,
                                              const float* __restrict__ beta,
                                              float* __restrict__ out) {
    const int wid  = threadIdx.x >> 5;
    const int lane = threadIdx.x & 31;
    const int i    = blockIdx.x * 8 + wid;
    if (i >= N_NODES) return;

    const int off = g_off[i];
    const int deg = g_deg[i];

    float q[8];
    {
        const float4* qp = reinterpret_cast<const float4*>(&g_qs[(size_t)i * 512 + lane * 8]);
        float4 q0 = __ldg(qp), q1 = __ldg(qp + 1);
        const float sc = 0.17677669529663689f;   // 1/sqrt(32)
        q[0] = q0.x * sc; q[1] = q0.y * sc; q[2] = q0.z * sc; q[3] = q0.w * sc;
        q[4] = q1.x * sc; q[5] = q1.y * sc; q[6] = q1.z * sc; q[7] = q1.w * sc;
    }

    float acc[8];
#pragma unroll
    for (int d = 0; d < 8; d++) acc[d] = 0.f;
    float denom = 0.f;

    int j = 0;
    for (; j + 2 <= deg; j += 2) {
        int s0 = __ldg(&g_srcSorted[off + j]);
        int s1 = __ldg(&g_srcSorted[off + j + 1]);
        uint4 ka = __ldg(reinterpret_cast<const uint4*>(&g_k[(size_t)s0 * 256 + lane * 8]));
        uint4 va = __ldg(reinterpret_cast<const uint4*>(&g_v[(size_t)s0 * 256 + lane * 8]));
        uint4 kb = __ldg(reinterpret_cast<const uint4*>(&g_k[(size_t)s1 * 256 + lane * 8]));
        uint4 vb = __ldg(reinterpret_cast<const uint4*>(&g_v[(size_t)s1 * 256 + lane * 8]));
        unsigned ua[4] = {ka.x, ka.y, ka.z, ka.w};
        unsigned ub[4] = {kb.x, kb.y, kb.z, kb.w};
        float p0 = 0.f, p1 = 0.f;
#pragma unroll
        for (int t = 0; t < 4; t++) {
            float2 fa = __bfloat1622float2(*reinterpret_cast<__nv_bfloat162*>(&ua[t]));
            float2 fb = __bfloat1622float2(*reinterpret_cast<__nv_bfloat162*>(&ub[t]));
            p0 = fmaf(q[2 * t], fa.x, fmaf(q[2 * t + 1], fa.y, p0));
            p1 = fmaf(q[2 * t], fb.x, fmaf(q[2 * t + 1], fb.y, p1));
        }
        p0 += __shfl_xor_sync(0xFFFFFFFFu, p0, 1);
        p0 += __shfl_xor_sync(0xFFFFFFFFu, p0, 2);
        p1 += __shfl_xor_sync(0xFFFFFFFFu, p1, 1);
        p1 += __shfl_xor_sync(0xFFFFFFFFu, p1, 2);
        float w0 = __expf(p0);
        float w1 = __expf(p1);
        denom += w0 + w1;
        unsigned wa[4] = {va.x, va.y, va.z, va.w};
        unsigned wb[4] = {vb.x, vb.y, vb.z, vb.w};
#pragma unroll
        for (int t = 0; t < 4; t++) {
            float2 fa = __bfloat1622float2(*reinterpret_cast<__nv_bfloat162*>(&wa[t]));
            float2 fb = __bfloat1622float2(*reinterpret_cast<__nv_bfloat162*>(&wb[t]));
            acc[2 * t]     = fmaf(w0, fa.x, fmaf(w1, fb.x, acc[2 * t]));
            acc[2 * t + 1] = fmaf(w0, fa.y, fmaf(w1, fb.y, acc[2 * t + 1]));
        }
    }
    if (j < deg) {
        int s0 = __ldg(&g_srcSorted[off + j]);
        uint4 ka = __ldg(reinterpret_cast<const uint4*>(&g_k[(size_t)s0 * 256 + lane * 8]));
        uint4 va = __ldg(reinterpret_cast<const uint4*>(&g_v[(size_t)s0 * 256 + lane * 8]));
        unsigned ua[4] = {ka.x, ka.y, ka.z, ka.w};
        float p0 = 0.f;
#pragma unroll
        for (int t = 0; t < 4; t++) {
            float2 fa = __bfloat1622float2(*reinterpret_cast<__nv_bfloat162*>(&ua[t]));
            p0 = fmaf(q[2 * t], fa.x, fmaf(q[2 * t + 1], fa.y, p0));
        }
        p0 += __shfl_xor_sync(0xFFFFFFFFu, p0, 1);
        p0 += __shfl_xor_sync(0xFFFFFFFFu, p0, 2);
        float w0 = __expf(p0);
        denom += w0;
        unsigned wa[4] = {va.x, va.y, va.z, va.w};
#pragma unroll
        for (int t = 0; t < 4; t++) {
            float2 fa = __bfloat1622float2(*reinterpret_cast<__nv_bfloat162*>(&wa[t]));
            acc[2 * t]     = fmaf(w0, fa.x, acc[2 * t]);
            acc[2 * t + 1] = fmaf(w0, fa.y, acc[2 * t + 1]);
        }
    }

    const float inv_dn = (deg > 0) ? (1.f / denom) : 0.f;

    float4 sk0, sk1, xv0, xv1;
    {
        const float4* sp = reinterpret_cast<const float4*>(&g_qs[(size_t)i * 512 + 256 + lane * 8]);
        sk0 = __ldg(sp); sk1 = __ldg(sp + 1);
        const float4* xp = reinterpret_cast<const float4*>(&x[(size_t)i * HID + lane * 8]);
        xv0 = __ldg(xp); xv1 = __ldg(xp + 1);
    }
    float skp[8] = {sk0.x, sk0.y, sk0.z, sk0.w, sk1.x, sk1.y, sk1.z, sk1.w};
    float xv[8]  = {xv0.x, xv0.y, xv0.z, xv0.w, xv1.x, xv1.y, xv1.z, xv1.w};

    float y[8];
    float s1 = 0.f, s2 = 0.f;
#pragma unroll
    for (int d = 0; d < 8; d++) {
        float o    = acc[d] * inv_dn + skp[d];
        float gelu = 0.5f * o * (1.f + erff(o * 0.70710678118654752f));
        float yy   = xv[d] + gelu;
        y[d] = yy;
        s1 += yy;
        s2 += yy * yy;
    }
#pragma unroll
    for (int o2 = 16; o2 > 0; o2 >>= 1) {
        s1 += __shfl_xor_sync(0xFFFFFFFFu, s1, o2);
        s2 += __shfl_xor_sync(0xFFFFFFFFu, s2, o2);
    }
    float mu  = s1 * (1.f / 256.f);
    float var = s2 * (1.f / 256.f) - mu * mu;
    float inv = rsqrtf(var + 1e-5f);

    const float4* gp = reinterpret_cast<const float4*>(&gamma[lane * 8]);
    const float4* bp = reinterpret_cast<const float4*>(&beta[lane * 8]);
    float4 g0 = __ldg(gp), g1 = __ldg(gp + 1);
    float4 b0 = __ldg(bp), b1 = __ldg(bp + 1);
    float gm[8] = {g0.x, g0.y, g0.z, g0.w, g1.x, g1.y, g1.z, g1.w};
    float bt[8] = {b0.x, b0.y, b0.z, b0.w, b1.x, b1.y, b1.z, b1.w};

    float4 o0, o1;
    o0.x = (y[0] - mu) * inv * gm[0] + bt[0];
    o0.y = (y[1] - mu) * inv * gm[1] + bt[1];
    o0.z = (y[2] - mu) * inv * gm[2] + bt[2];
    o0.w = (y[3] - mu) * inv * gm[3] + bt[3];
    o1.x = (y[4] - mu) * inv * gm[4] + bt[4];
    o1.y = (y[5] - mu) * inv * gm[5] + bt[5];
    o1.z = (y[6] - mu) * inv * gm[6] + bt[6];
    o1.w = (y[7] - mu) * inv * gm[7] + bt[7];
    float4* op = reinterpret_cast<float4*>(&out[(size_t)i * HID + lane * 8]);
    op[0] = o0;
    op[1] = o1;
}

// ---------------- launch: 3-way fork (gemm chain / cvtX / CSR), join at attn ----
// str0: packW -> gemm -> attn.  s3: cvtX (joins str0 before gemm).
// s2: zero -> count -> scan1 -> scan3 -> scatter (joins str0 before attn).
// Issue order keeps k_gemm as launch #4 for the ncu window.
extern "C" void kernel_launch(void* const* d_in, const int* in_sizes, int n_in,
                              void* d_out, int out_size) {
    const float* x     = (const float*)d_in[0];
    const int*   ei    = (const int*)d_in[1];     // int32 (JAX x64 disabled)
    const float* Wq    = (const float*)d_in[2];
    const float* bq    = (const float*)d_in[3];
    const float* Wk    = (const float*)d_in[4];
    const float* bk    = (const float*)d_in[5];
    const float* Wv    = (const float*)d_in[6];
    const float* bv    = (const float*)d_in[7];
    const float* Wsk   = (const float*)d_in[8];
    const float* bsk   = (const float*)d_in[9];
    const float* gamma = (const float*)d_in[10];
    const float* beta  = (const float*)d_in[11];
    float* out = (float*)d_out;

    static cudaStream_t s2 = nullptr, s3 = nullptr;
    static cudaEvent_t evFork = nullptr, evJoin = nullptr, evCvt = nullptr;
    if (s2 == nullptr) {
        cudaStreamCreateWithFlags(&s2, cudaStreamNonBlocking);
        cudaStreamCreateWithFlags(&s3, cudaStreamNonBlocking);
        cudaEventCreateWithFlags(&evFork, cudaEventDisableTiming);
        cudaEventCreateWithFlags(&evJoin, cudaEventDisableTiming);
        cudaEventCreateWithFlags(&evCvt, cudaEventDisableTiming);
    }

    // fork: side streams ordered after whatever precedes this launch sequence
    cudaEventRecord(evFork, 0);
    cudaStreamWaitEvent(s2, evFork, 0);
    cudaStreamWaitEvent(s3, evFork, 0);

    k_packW<<<(128 * 16 * 32 + 255) / 256, 256>>>(Wq, Wk, Wv, Wsk, bq, bk, bv, bsk); // 1 (str0)
    k_cvtX<<<(N_NODES * 32 + 255) / 256, 256, 0, s3>>>(x);                            // 2 (s3)
    k_zero<<<(N_NODES + 255) / 256, 256, 0, s2>>>();                                  // 3 (s2)

    // gemm needs cvtX done
    cudaEventRecord(evCvt, s3);
    cudaStreamWaitEvent(0, evCvt, 0);
    dim3 gg(NQKV / GBN, (N_NODES + GBM - 1) / GBM);
    k_gemm<<<gg, 256>>>();                                                            // 4 (str0, profiled)

    k_count<<<(E_EDGES + 255) / 256, 256, 0, s2>>>(ei);                               // 5 (s2)
    k_scan1<<<NBLK, SCAN_B, 0, s2>>>();                                               // 6 (s2)
    k_scan3<<<(N_NODES + 255) / 256, 256, 0, s2>>>();                                 // 7 (s2)
    k_scatter<<<(E_EDGES + 255) / 256, 256, 0, s2>>>(ei);                             // 8 (s2)

    // join: attn needs both chains
    cudaEventRecord(evJoin, s2);
    cudaStreamWaitEvent(0, evJoin, 0);
    k_attn<<<(N_NODES + 7) / 8, 256>>>(x, gamma, beta, out);                          // 9 (str0)
}

// round 16
// speedup vs baseline: 1.1533x; 1.1533x over previous
#include <cuda_runtime.h>
#include <cuda_bf16.h>
#include <cuda_fp16.h>
#include <math.h>

#define N_NODES 50000
#define HID     256
#define NQKV    1024
#define E_EDGES 800000
#define SCAN_B  1024
#define NBLK    ((N_NODES + SCAN_B - 1) / SCAN_B)   // 49

// ---------------- device scratch (no runtime allocation allowed) ----------------
__device__ __align__(16) float  g_qs[N_NODES * 512];        // q(0:256) | skip(256:512), fp32
__device__ __align__(16) __nv_bfloat16 g_k[N_NODES * 256];
__device__ __align__(16) __nv_bfloat16 g_v[N_NODES * 256];
__device__ __align__(16) __half g_x16[N_NODES * 256];       // fp16 copy of X, 25.6 MB
__device__ __align__(16) uint2  g_Wfrag16[128 * 16 * 32];   // fp16 B-fragments (m16n8k16), 512 KB
__device__ float g_bcat[NQKV];
__device__ int   g_deg[N_NODES];
__device__ int   g_off[N_NODES];
__device__ int   g_cur[N_NODES];
__device__ int   g_srcSorted[E_EDGES];
__device__ int   g_bsum[NBLK];

// ---------------- helpers ----------------
__device__ __forceinline__ void mma_f16(float* d, const unsigned* a, const unsigned* b,
                                        const float* c) {
    asm volatile(
        "mma.sync.aligned.m16n8k16.row.col.f32.f16.f16.f32 "
        "{%0,%1,%2,%3}, {%4,%5,%6,%7}, {%8,%9}, {%10,%11,%12,%13};\n"
        : "=f"(d[0]), "=f"(d[1]), "=f"(d[2]), "=f"(d[3])
        : "r"(a[0]), "r"(a[1]), "r"(a[2]), "r"(a[3]),
          "r"(b[0]), "r"(b[1]),
          "f"(c[0]), "f"(c[1]), "f"(c[2]), "f"(c[3]));
}

__device__ __forceinline__ void ldsm_x4(unsigned& r0, unsigned& r1, unsigned& r2,
                                        unsigned& r3, unsigned addr) {
    asm volatile("ldmatrix.sync.aligned.m8n8.x4.shared.b16 {%0,%1,%2,%3}, [%4];"
                 : "=r"(r0), "=r"(r1), "=r"(r2), "=r"(r3) : "r"(addr));
}

__device__ __forceinline__ unsigned smem_u32(const void* p) {
    return (unsigned)__cvta_generic_to_shared(p);
}

__device__ __forceinline__ void cp_async16(unsigned dst, const void* src, int src_bytes) {
    asm volatile("cp.async.cg.shared.global [%0], [%1], 16, %2;"
                 :: "r"(dst), "l"(src), "r"(src_bytes));
}

// ---------------- pack weights into fp16 m16n8k16 B-fragment order (+bias) ------
__global__ void k_packW(const float* __restrict__ Wq, const float* __restrict__ Wk,
                        const float* __restrict__ Wv, const float* __restrict__ Ws,
                        const float* __restrict__ bq, const float* __restrict__ bk,
                        const float* __restrict__ bv, const float* __restrict__ bs) {
    int t = blockIdx.x * blockDim.x + threadIdx.x;
    if (t < 128 * 16 * 32) {
        int lane = t & 31;
        int kb   = (t >> 5) & 15;
        int nb   = t >> 9;
        int n_glob = nb * 8 + (lane >> 2);
        int k0     = kb * 16 + (lane & 3) * 2;
        int seg  = n_glob >> 8;
        int ncol = n_glob & 255;
        const float* W = (seg == 0) ? Wq : (seg == 1) ? Wk : (seg == 2) ? Wv : Ws;
        __half2 h0 = __floats2half2_rn(W[k0 * HID + ncol],       W[(k0 + 1) * HID + ncol]);
        __half2 h1 = __floats2half2_rn(W[(k0 + 8) * HID + ncol], W[(k0 + 9) * HID + ncol]);
        uint2 u;
        u.x = *reinterpret_cast<unsigned*>(&h0);
        u.y = *reinterpret_cast<unsigned*>(&h1);
        g_Wfrag16[t] = u;
    }
    if (t < NQKV) {
        int seg = t >> 8, idx = t & 255;
        const float* b = (seg == 0) ? bq : (seg == 1) ? bk : (seg == 2) ? bv : bs;
        g_bcat[t] = b[idx];
    }
}

// ---------------- X -> fp16 (side stream, overlaps packW) ----------------
__global__ void k_cvtX(const float* __restrict__ X) {
    int t = blockIdx.x * blockDim.x + threadIdx.x;     // over N*256/8
    if (t >= N_NODES * 32) return;
    const float4* xp = reinterpret_cast<const float4*>(X) + t * 2;
    float4 v0 = __ldg(xp), v1 = __ldg(xp + 1);
    __half2 h0 = __floats2half2_rn(v0.x, v0.y);
    __half2 h1 = __floats2half2_rn(v0.z, v0.w);
    __half2 h2 = __floats2half2_rn(v1.x, v1.y);
    __half2 h3 = __floats2half2_rn(v1.z, v1.w);
    uint4 u;
    u.x = *reinterpret_cast<unsigned*>(&h0);
    u.y = *reinterpret_cast<unsigned*>(&h1);
    u.z = *reinterpret_cast<unsigned*>(&h2);
    u.w = *reinterpret_cast<unsigned*>(&h3);
    reinterpret_cast<uint4*>(g_x16)[t] = u;
}

// ---------------- fp16 tensor-core GEMM, 2-stage cp.async (R13/R14 winner) ------
// No occupancy clamp: launch_bounds(256,3) spilled the mainloop (R15 evidence:
// L1 55->71%, tensor 39->29%). regs ~93 / 2 CTAs per SM is the operating point.
#define GBM 128
#define GBN 128
#define GBK 32
#define ASTR 40   // fp16 elements per A row
__global__ __launch_bounds__(256) void k_gemm() {
    __shared__ __align__(16) __half As[2][GBM * ASTR];   // 2 x 10240 B
    __shared__ __align__(16) uint2  Bs[2][1024];         // 2 x 8192 B

    const int bm   = blockIdx.y * GBM;
    const int bn   = blockIdx.x * GBN;
    const int tid  = threadIdx.x;
    const int wid  = tid >> 5;
    const int lane = tid & 31;
    const int warp_m = wid >> 2;
    const int warp_n = wid & 3;
    const int gid = lane >> 2;
    const int tig = lane & 3;
    const int nb0 = bn >> 3;

    auto loadA = [&](int stage, int kbase) {
#pragma unroll
        for (int l = 0; l < 2; l++) {
            int u   = tid + l * 256;
            int row = u >> 2;
            int c8  = (u & 3) * 8;
            int gr  = bm + row;
            cp_async16(smem_u32(&As[stage][row * ASTR + c8]),
                       &g_x16[(size_t)gr * 256 + kbase + c8], gr < N_NODES ? 16 : 0);
        }
    };
    auto loadB = [&](int stage, int kbase) {
        int kb0 = kbase >> 4;
#pragma unroll
        for (int l = 0; l < 2; l++) {
            int u      = tid + l * 256;
            int group  = u >> 4;
            int within = u & 15;
            const char* src = reinterpret_cast<const char*>(g_Wfrag16)
                            + ((size_t)((nb0 + (group >> 1)) * 16 + kb0 + (group & 1)) * 256)
                            + within * 16;
            cp_async16(smem_u32(&Bs[stage][0]) + u * 16, src, 16);
        }
    };

    float acc[4][4][4];
#pragma unroll
    for (int mf = 0; mf < 4; mf++)
#pragma unroll
        for (int nf = 0; nf < 4; nf++)
#pragma unroll
            for (int r = 0; r < 4; r++) acc[mf][nf][r] = 0.f;

    loadA(0, 0);
    loadB(0, 0);
    asm volatile("cp.async.commit_group;");

    const int ltile = lane >> 3;
    const int lrow  = lane & 7;
    const int arow0 = warp_m * 64 + lrow + (ltile & 1) * 8;
    const int acol0 = (ltile >> 1) * 8;

    for (int k0 = 0; k0 < HID; k0 += GBK) {
        const int buf = (k0 >> 5) & 1;
        const bool more = (k0 + GBK) < HID;
        if (more) {
            loadA(buf ^ 1, k0 + GBK);
            loadB(buf ^ 1, k0 + GBK);
            asm volatile("cp.async.commit_group;");
            asm volatile("cp.async.wait_group 1;");
        } else {
            asm volatile("cp.async.wait_group 0;");
        }
        __syncthreads();

        const unsigned abase = smem_u32(&As[buf][0]);
#pragma unroll
        for (int ks = 0; ks < 2; ks++) {
            const int kk = ks * 16;
            unsigned bfr[4][2];
#pragma unroll
            for (int nf = 0; nf < 4; nf++) {
                uint2 w = Bs[buf][((warp_n * 4 + nf) * 2 + ks) * 32 + lane];
                bfr[nf][0] = w.x;
                bfr[nf][1] = w.y;
            }
            unsigned afr[4][4];
#pragma unroll
            for (int mf = 0; mf < 4; mf++)
                ldsm_x4(afr[mf][0], afr[mf][1], afr[mf][2], afr[mf][3],
                        abase + ((arow0 + mf * 16) * ASTR + kk + acol0) * 2);
#pragma unroll
            for (int mf = 0; mf < 4; mf++)
#pragma unroll
                for (int nf = 0; nf < 4; nf++)
                    mma_f16(acc[mf][nf], afr[mf], bfr[nf], acc[mf][nf]);
        }
        __syncthreads();
    }

    const int seg = bn >> 8;
    const int segbase = bn & 255;
#pragma unroll
    for (int mf = 0; mf < 4; mf++) {
#pragma unroll
        for (int nf = 0; nf < 4; nf++) {
            int lcol = warp_n * 32 + nf * 8 + tig * 2;
            int cn   = bn + lcol;
            int scol = segbase + lcol;
            float b0 = g_bcat[cn], b1 = g_bcat[cn + 1];
#pragma unroll
            for (int half = 0; half < 2; half++) {
                int row = bm + warp_m * 64 + mf * 16 + gid + half * 8;
                if (row >= N_NODES) continue;
                float o0 = acc[mf][nf][half * 2 + 0] + b0;
                float o1 = acc[mf][nf][half * 2 + 1] + b1;
                if (seg == 0) {
                    *reinterpret_cast<float2*>(&g_qs[(size_t)row * 512 + scol]) =
                        make_float2(o0, o1);
                } else if (seg == 3) {
                    *reinterpret_cast<float2*>(&g_qs[(size_t)row * 512 + 256 + scol]) =
                        make_float2(o0, o1);
                } else {
                    __nv_bfloat162 h = __float22bfloat162_rn(make_float2(o0, o1));
                    __nv_bfloat16* dst = (seg == 1) ? g_k : g_v;
                    *reinterpret_cast<__nv_bfloat162*>(&dst[(size_t)row * 256 + scol]) = h;
                }
            }
        }
    }
}

// ---------------- CSR build (dst-grouped, runs on side stream) ----------------
__global__ void k_zero() {
    int i = blockIdx.x * blockDim.x + threadIdx.x;
    if (i < N_NODES) g_deg[i] = 0;
}

__global__ void k_count(const int* __restrict__ ei) {
    int e = blockIdx.x * blockDim.x + threadIdx.x;
    if (e < E_EDGES) {
        int dst = ei[E_EDGES + e];
        if ((unsigned)dst < N_NODES) atomicAdd(&g_deg[dst], 1);
    }
}

__global__ __launch_bounds__(SCAN_B) void k_scan1() {
    int b = blockIdx.x, t = threadIdx.x;
    int i = b * SCAN_B + t;
    int v = (i < N_NODES) ? g_deg[i] : 0;
    int lane = t & 31, w = t >> 5;
    int x = v;
#pragma unroll
    for (int o = 1; o < 32; o <<= 1) {
        int y = __shfl_up_sync(0xFFFFFFFFu, x, o);
        if (lane >= o) x += y;
    }
    __shared__ int wsum[32];
    if (lane == 31) wsum[w] = x;
    __syncthreads();
    if (w == 0) {
        int s = wsum[lane];
#pragma unroll
        for (int o = 1; o < 32; o <<= 1) {
            int y = __shfl_up_sync(0xFFFFFFFFu, s, o);
            if (lane >= o) s += y;
        }
        wsum[lane] = s;
    }
    __syncthreads();
    int incl = x + (w > 0 ? wsum[w - 1] : 0);
    if (i < N_NODES) g_off[i] = incl - v;
    if (t == SCAN_B - 1) g_bsum[b] = incl;
}

__global__ void k_scan3() {
    __shared__ int pre;
    int b = blockIdx.x;
    if (threadIdx.x == 0) {
        int gb = (b << 8) / SCAN_B;
        int s = 0;
        for (int t = 0; t < gb; t++) s += g_bsum[t];
        pre = s;
    }
    __syncthreads();
    int i = (b << 8) + threadIdx.x;
    if (i < N_NODES) {
        int o = g_off[i] + pre;
        g_off[i] = o;
        g_cur[i] = o;
    }
}

__global__ void k_scatter(const int* __restrict__ ei) {
    int e = blockIdx.x * blockDim.x + threadIdx.x;
    if (e < E_EDGES) {
        int src = ei[e];
        int dst = ei[E_EDGES + e];
        if ((unsigned)src < N_NODES && (unsigned)dst < N_NODES) {
            int p = atomicAdd(&g_cur[dst], 1);
            if ((unsigned)p < E_EDGES) g_srcSorted[p] = src;
        }
    }
}

// ---------------- fused attention + skip + GELU + residual + LayerNorm ----------------
// WARP-PER-NODE (R10 winner, unchanged; at LTS gather roofline).
__global__ __launch_bounds__(256) void k_attn(const float* __restrict__ x,
                                              const float* __restrict__ gamma,
                                              const float* __restrict__ beta,
                                              float* __restrict__ out) {
    const int wid  = threadIdx.x >> 5;
    const int lane = threadIdx.x & 31;
    const int i    = blockIdx.x * 8 + wid;
    if (i >= N_NODES) return;

    const int off = g_off[i];
    const int deg = g_deg[i];

    float q[8];
    {
        const float4* qp = reinterpret_cast<const float4*>(&g_qs[(size_t)i * 512 + lane * 8]);
        float4 q0 = __ldg(qp), q1 = __ldg(qp + 1);
        const float sc = 0.17677669529663689f;   // 1/sqrt(32)
        q[0] = q0.x * sc; q[1] = q0.y * sc; q[2] = q0.z * sc; q[3] = q0.w * sc;
        q[4] = q1.x * sc; q[5] = q1.y * sc; q[6] = q1.z * sc; q[7] = q1.w * sc;
    }

    float acc[8];
#pragma unroll
    for (int d = 0; d < 8; d++) acc[d] = 0.f;
    float denom = 0.f;

    int j = 0;
    for (; j + 2 <= deg; j += 2) {
        int s0 = __ldg(&g_srcSorted[off + j]);
        int s1 = __ldg(&g_srcSorted[off + j + 1]);
        uint4 ka = __ldg(reinterpret_cast<const uint4*>(&g_k[(size_t)s0 * 256 + lane * 8]));
        uint4 va = __ldg(reinterpret_cast<const uint4*>(&g_v[(size_t)s0 * 256 + lane * 8]));
        uint4 kb = __ldg(reinterpret_cast<const uint4*>(&g_k[(size_t)s1 * 256 + lane * 8]));
        uint4 vb = __ldg(reinterpret_cast<const uint4*>(&g_v[(size_t)s1 * 256 + lane * 8]));
        unsigned ua[4] = {ka.x, ka.y, ka.z, ka.w};
        unsigned ub[4] = {kb.x, kb.y, kb.z, kb.w};
        float p0 = 0.f, p1 = 0.f;
#pragma unroll
        for (int t = 0; t < 4; t++) {
            float2 fa = __bfloat1622float2(*reinterpret_cast<__nv_bfloat162*>(&ua[t]));
            float2 fb = __bfloat1622float2(*reinterpret_cast<__nv_bfloat162*>(&ub[t]));
            p0 = fmaf(q[2 * t], fa.x, fmaf(q[2 * t + 1], fa.y, p0));
            p1 = fmaf(q[2 * t], fb.x, fmaf(q[2 * t + 1], fb.y, p1));
        }
        p0 += __shfl_xor_sync(0xFFFFFFFFu, p0, 1);
        p0 += __shfl_xor_sync(0xFFFFFFFFu, p0, 2);
        p1 += __shfl_xor_sync(0xFFFFFFFFu, p1, 1);
        p1 += __shfl_xor_sync(0xFFFFFFFFu, p1, 2);
        float w0 = __expf(p0);
        float w1 = __expf(p1);
        denom += w0 + w1;
        unsigned wa[4] = {va.x, va.y, va.z, va.w};
        unsigned wb[4] = {vb.x, vb.y, vb.z, vb.w};
#pragma unroll
        for (int t = 0; t < 4; t++) {
            float2 fa = __bfloat1622float2(*reinterpret_cast<__nv_bfloat162*>(&wa[t]));
            float2 fb = __bfloat1622float2(*reinterpret_cast<__nv_bfloat162*>(&wb[t]));
            acc[2 * t]     = fmaf(w0, fa.x, fmaf(w1, fb.x, acc[2 * t]));
            acc[2 * t + 1] = fmaf(w0, fa.y, fmaf(w1, fb.y, acc[2 * t + 1]));
        }
    }
    if (j < deg) {
        int s0 = __ldg(&g_srcSorted[off + j]);
        uint4 ka = __ldg(reinterpret_cast<const uint4*>(&g_k[(size_t)s0 * 256 + lane * 8]));
        uint4 va = __ldg(reinterpret_cast<const uint4*>(&g_v[(size_t)s0 * 256 + lane * 8]));
        unsigned ua[4] = {ka.x, ka.y, ka.z, ka.w};
        float p0 = 0.f;
#pragma unroll
        for (int t = 0; t < 4; t++) {
            float2 fa = __bfloat1622float2(*reinterpret_cast<__nv_bfloat162*>(&ua[t]));
            p0 = fmaf(q[2 * t], fa.x, fmaf(q[2 * t + 1], fa.y, p0));
        }
        p0 += __shfl_xor_sync(0xFFFFFFFFu, p0, 1);
        p0 += __shfl_xor_sync(0xFFFFFFFFu, p0, 2);
        float w0 = __expf(p0);
        denom += w0;
        unsigned wa[4] = {va.x, va.y, va.z, va.w};
#pragma unroll
        for (int t = 0; t < 4; t++) {
            float2 fa = __bfloat1622float2(*reinterpret_cast<__nv_bfloat162*>(&wa[t]));
            acc[2 * t]     = fmaf(w0, fa.x, acc[2 * t]);
            acc[2 * t + 1] = fmaf(w0, fa.y, acc[2 * t + 1]);
        }
    }

    const float inv_dn = (deg > 0) ? (1.f / denom) : 0.f;

    float4 sk0, sk1, xv0, xv1;
    {
        const float4* sp = reinterpret_cast<const float4*>(&g_qs[(size_t)i * 512 + 256 + lane * 8]);
        sk0 = __ldg(sp); sk1 = __ldg(sp + 1);
        const float4* xp = reinterpret_cast<const float4*>(&x[(size_t)i * HID + lane * 8]);
        xv0 = __ldg(xp); xv1 = __ldg(xp + 1);
    }
    float skp[8] = {sk0.x, sk0.y, sk0.z, sk0.w, sk1.x, sk1.y, sk1.z, sk1.w};
    float xv[8]  = {xv0.x, xv0.y, xv0.z, xv0.w, xv1.x, xv1.y, xv1.z, xv1.w};

    float y[8];
    float s1 = 0.f, s2 = 0.f;
#pragma unroll
    for (int d = 0; d < 8; d++) {
        float o    = acc[d] * inv_dn + skp[d];
        float gelu = 0.5f * o * (1.f + erff(o * 0.70710678118654752f));
        float yy   = xv[d] + gelu;
        y[d] = yy;
        s1 += yy;
        s2 += yy * yy;
    }
#pragma unroll
    for (int o2 = 16; o2 > 0; o2 >>= 1) {
        s1 += __shfl_xor_sync(0xFFFFFFFFu, s1, o2);
        s2 += __shfl_xor_sync(0xFFFFFFFFu, s2, o2);
    }
    float mu  = s1 * (1.f / 256.f);
    float var = s2 * (1.f / 256.f) - mu * mu;
    float inv = rsqrtf(var + 1e-5f);

    const float4* gp = reinterpret_cast<const float4*>(&gamma[lane * 8]);
    const float4* bp = reinterpret_cast<const float4*>(&beta[lane * 8]);
    float4 g0 = __ldg(gp), g1 = __ldg(gp + 1);
    float4 b0 = __ldg(bp), b1 = __ldg(bp + 1);
    float gm[8] = {g0.x, g0.y, g0.z, g0.w, g1.x, g1.y, g1.z, g1.w};
    float bt[8] = {b0.x, b0.y, b0.z, b0.w, b1.x, b1.y, b1.z, b1.w};

    float4 o0, o1;
    o0.x = (y[0] - mu) * inv * gm[0] + bt[0];
    o0.y = (y[1] - mu) * inv * gm[1] + bt[1];
    o0.z = (y[2] - mu) * inv * gm[2] + bt[2];
    o0.w = (y[3] - mu) * inv * gm[3] + bt[3];
    o1.x = (y[4] - mu) * inv * gm[4] + bt[4];
    o1.y = (y[5] - mu) * inv * gm[5] + bt[5];
    o1.z = (y[6] - mu) * inv * gm[6] + bt[6];
    o1.w = (y[7] - mu) * inv * gm[7] + bt[7];
    float4* op = reinterpret_cast<float4*>(&out[(size_t)i * HID + lane * 8]);
    op[0] = o0;
    op[1] = o1;
}

// ---------------- launch: 3-way fork (gemm chain / cvtX / CSR), join at attn ----
extern "C" void kernel_launch(void* const* d_in, const int* in_sizes, int n_in,
                              void* d_out, int out_size) {
    const float* x     = (const float*)d_in[0];
    const int*   ei    = (const int*)d_in[1];     // int32 (JAX x64 disabled)
    const float* Wq    = (const float*)d_in[2];
    const float* bq    = (const float*)d_in[3];
    const float* Wk    = (const float*)d_in[4];
    const float* bk    = (const float*)d_in[5];
    const float* Wv    = (const float*)d_in[6];
    const float* bv    = (const float*)d_in[7];
    const float* Wsk   = (const float*)d_in[8];
    const float* bsk   = (const float*)d_in[9];
    const float* gamma = (const float*)d_in[10];
    const float* beta  = (const float*)d_in[11];
    float* out = (float*)d_out;

    static cudaStream_t s2 = nullptr, s3 = nullptr;
    static cudaEvent_t evFork = nullptr, evJoin = nullptr, evCvt = nullptr;
    if (s2 == nullptr) {
        cudaStreamCreateWithFlags(&s2, cudaStreamNonBlocking);
        cudaStreamCreateWithFlags(&s3, cudaStreamNonBlocking);
        cudaEventCreateWithFlags(&evFork, cudaEventDisableTiming);
        cudaEventCreateWithFlags(&evJoin, cudaEventDisableTiming);
        cudaEventCreateWithFlags(&evCvt, cudaEventDisableTiming);
    }

    cudaEventRecord(evFork, 0);
    cudaStreamWaitEvent(s2, evFork, 0);
    cudaStreamWaitEvent(s3, evFork, 0);

    k_packW<<<(128 * 16 * 32 + 255) / 256, 256>>>(Wq, Wk, Wv, Wsk, bq, bk, bv, bsk); // 1 (str0)
    k_cvtX<<<(N_NODES * 32 + 255) / 256, 256, 0, s3>>>(x);                            // 2 (s3)
    k_zero<<<(N_NODES + 255) / 256, 256, 0, s2>>>();                                  // 3 (s2)

    cudaEventRecord(evCvt, s3);
    cudaStreamWaitEvent(0, evCvt, 0);
    dim3 gg(NQKV / GBN, (N_NODES + GBM - 1) / GBM);
    k_gemm<<<gg, 256>>>();                                                            // 4 (str0, profiled)

    k_count<<<(E_EDGES + 255) / 256, 256, 0, s2>>>(ei);                               // 5 (s2)
    k_scan1<<<NBLK, SCAN_B, 0, s2>>>();                                               // 6 (s2)
    k_scan3<<<(N_NODES + 255) / 256, 256, 0, s2>>>();                                 // 7 (s2)
    k_scatter<<<(E_EDGES + 255) / 256, 256, 0, s2>>>(ei);                             // 8 (s2)

    cudaEventRecord(evJoin, s2);
    cudaStreamWaitEvent(0, evJoin, 0);
    k_attn<<<(N_NODES + 7) / 8, 256>>>(x, gamma, beta, out);                          // 9 (str0)
}

// round 17
// speedup vs baseline: 1.2264x; 1.0633x over previous
#include <cuda_runtime.h>
#include <cuda_bf16.h>
#include <cuda_fp16.h>
#include <math.h>

#define N_NODES 50000
#define HID     256
#define NQKV    1024
#define E_EDGES 800000
#define SCAN_B  1024
#define NBLK    ((N_NODES + SCAN_B - 1) / SCAN_B)   // 49

// ---------------- device scratch (no runtime allocation allowed) ----------------
__device__ __align__(16) float  g_qs[N_NODES * 512];        // q(0:256) | skip(256:512), fp32
__device__ __align__(16) __nv_bfloat16 g_k[N_NODES * 256];
__device__ __align__(16) __nv_bfloat16 g_v[N_NODES * 256];
__device__ __align__(16) __half g_x16[N_NODES * 256];       // fp16 copy of X, 25.6 MB
__device__ __align__(16) uint2  g_Wfrag16[128 * 16 * 32];   // fp16 B-fragments (m16n8k16), 512 KB
__device__ float g_bcat[NQKV];
__device__ int   g_deg[N_NODES];   // zero-initialized at load; self-cleaned by k_attn each run
__device__ int   g_off[N_NODES];
__device__ int   g_cur[N_NODES];
__device__ int   g_srcSorted[E_EDGES];
__device__ int   g_bsum[NBLK];

// ---------------- helpers ----------------
__device__ __forceinline__ void mma_f16(float* d, const unsigned* a, const unsigned* b,
                                        const float* c) {
    asm volatile(
        "mma.sync.aligned.m16n8k16.row.col.f32.f16.f16.f32 "
        "{%0,%1,%2,%3}, {%4,%5,%6,%7}, {%8,%9}, {%10,%11,%12,%13};\n"
        : "=f"(d[0]), "=f"(d[1]), "=f"(d[2]), "=f"(d[3])
        : "r"(a[0]), "r"(a[1]), "r"(a[2]), "r"(a[3]),
          "r"(b[0]), "r"(b[1]),
          "f"(c[0]), "f"(c[1]), "f"(c[2]), "f"(c[3]));
}

__device__ __forceinline__ void ldsm_x4(unsigned& r0, unsigned& r1, unsigned& r2,
                                        unsigned& r3, unsigned addr) {
    asm volatile("ldmatrix.sync.aligned.m8n8.x4.shared.b16 {%0,%1,%2,%3}, [%4];"
                 : "=r"(r0), "=r"(r1), "=r"(r2), "=r"(r3) : "r"(addr));
}

__device__ __forceinline__ unsigned smem_u32(const void* p) {
    return (unsigned)__cvta_generic_to_shared(p);
}

__device__ __forceinline__ void cp_async16(unsigned dst, const void* src, int src_bytes) {
    asm volatile("cp.async.cg.shared.global [%0], [%1], 16, %2;"
                 :: "r"(dst), "l"(src), "r"(src_bytes));
}

// ---------------- pack weights into fp16 m16n8k16 B-fragment order (+bias) ------
__global__ void k_packW(const float* __restrict__ Wq, const float* __restrict__ Wk,
                        const float* __restrict__ Wv, const float* __restrict__ Ws,
                        const float* __restrict__ bq, const float* __restrict__ bk,
                        const float* __restrict__ bv, const float* __restrict__ bs) {
    int t = blockIdx.x * blockDim.x + threadIdx.x;
    if (t < 128 * 16 * 32) {
        int lane = t & 31;
        int kb   = (t >> 5) & 15;
        int nb   = t >> 9;
        int n_glob = nb * 8 + (lane >> 2);
        int k0     = kb * 16 + (lane & 3) * 2;
        int seg  = n_glob >> 8;
        int ncol = n_glob & 255;
        const float* W = (seg == 0) ? Wq : (seg == 1) ? Wk : (seg == 2) ? Wv : Ws;
        __half2 h0 = __floats2half2_rn(W[k0 * HID + ncol],       W[(k0 + 1) * HID + ncol]);
        __half2 h1 = __floats2half2_rn(W[(k0 + 8) * HID + ncol], W[(k0 + 9) * HID + ncol]);
        uint2 u;
        u.x = *reinterpret_cast<unsigned*>(&h0);
        u.y = *reinterpret_cast<unsigned*>(&h1);
        g_Wfrag16[t] = u;
    }
    if (t < NQKV) {
        int seg = t >> 8, idx = t & 255;
        const float* b = (seg == 0) ? bq : (seg == 1) ? bk : (seg == 2) ? bv : bs;
        g_bcat[t] = b[idx];
    }
}

// ---------------- X -> fp16 (side stream, overlaps packW) ----------------
__global__ void k_cvtX(const float* __restrict__ X) {
    int t = blockIdx.x * blockDim.x + threadIdx.x;     // over N*256/8
    if (t >= N_NODES * 32) return;
    const float4* xp = reinterpret_cast<const float4*>(X) + t * 2;
    float4 v0 = __ldg(xp), v1 = __ldg(xp + 1);
    __half2 h0 = __floats2half2_rn(v0.x, v0.y);
    __half2 h1 = __floats2half2_rn(v0.z, v0.w);
    __half2 h2 = __floats2half2_rn(v1.x, v1.y);
    __half2 h3 = __floats2half2_rn(v1.z, v1.w);
    uint4 u;
    u.x = *reinterpret_cast<unsigned*>(&h0);
    u.y = *reinterpret_cast<unsigned*>(&h1);
    u.z = *reinterpret_cast<unsigned*>(&h2);
    u.w = *reinterpret_cast<unsigned*>(&h3);
    reinterpret_cast<uint4*>(g_x16)[t] = u;
}

// ---------------- fp16 tensor-core GEMM, 2-stage cp.async (converged winner) ----
// No occupancy clamp: (256,3) spilled the mainloop (R15). regs ~93, 2 CTAs/SM.
#define GBM 128
#define GBN 128
#define GBK 32
#define ASTR 40   // fp16 elements per A row
__global__ __launch_bounds__(256) void k_gemm() {
    __shared__ __align__(16) __half As[2][GBM * ASTR];   // 2 x 10240 B
    __shared__ __align__(16) uint2  Bs[2][1024];         // 2 x 8192 B

    const int bm   = blockIdx.y * GBM;
    const int bn   = blockIdx.x * GBN;
    const int tid  = threadIdx.x;
    const int wid  = tid >> 5;
    const int lane = tid & 31;
    const int warp_m = wid >> 2;
    const int warp_n = wid & 3;
    const int gid = lane >> 2;
    const int tig = lane & 3;
    const int nb0 = bn >> 3;

    auto loadA = [&](int stage, int kbase) {
#pragma unroll
        for (int l = 0; l < 2; l++) {
            int u   = tid + l * 256;
            int row = u >> 2;
            int c8  = (u & 3) * 8;
            int gr  = bm + row;
            cp_async16(smem_u32(&As[stage][row * ASTR + c8]),
                       &g_x16[(size_t)gr * 256 + kbase + c8], gr < N_NODES ? 16 : 0);
        }
    };
    auto loadB = [&](int stage, int kbase) {
        int kb0 = kbase >> 4;
#pragma unroll
        for (int l = 0; l < 2; l++) {
            int u      = tid + l * 256;
            int group  = u >> 4;
            int within = u & 15;
            const char* src = reinterpret_cast<const char*>(g_Wfrag16)
                            + ((size_t)((nb0 + (group >> 1)) * 16 + kb0 + (group & 1)) * 256)
                            + within * 16;
            cp_async16(smem_u32(&Bs[stage][0]) + u * 16, src, 16);
        }
    };

    float acc[4][4][4];
#pragma unroll
    for (int mf = 0; mf < 4; mf++)
#pragma unroll
        for (int nf = 0; nf < 4; nf++)
#pragma unroll
            for (int r = 0; r < 4; r++) acc[mf][nf][r] = 0.f;

    loadA(0, 0);
    loadB(0, 0);
    asm volatile("cp.async.commit_group;");

    const int ltile = lane >> 3;
    const int lrow  = lane & 7;
    const int arow0 = warp_m * 64 + lrow + (ltile & 1) * 8;
    const int acol0 = (ltile >> 1) * 8;

    for (int k0 = 0; k0 < HID; k0 += GBK) {
        const int buf = (k0 >> 5) & 1;
        const bool more = (k0 + GBK) < HID;
        if (more) {
            loadA(buf ^ 1, k0 + GBK);
            loadB(buf ^ 1, k0 + GBK);
            asm volatile("cp.async.commit_group;");
            asm volatile("cp.async.wait_group 1;");
        } else {
            asm volatile("cp.async.wait_group 0;");
        }
        __syncthreads();

        const unsigned abase = smem_u32(&As[buf][0]);
#pragma unroll
        for (int ks = 0; ks < 2; ks++) {
            const int kk = ks * 16;
            unsigned bfr[4][2];
#pragma unroll
            for (int nf = 0; nf < 4; nf++) {
                uint2 w = Bs[buf][((warp_n * 4 + nf) * 2 + ks) * 32 + lane];
                bfr[nf][0] = w.x;
                bfr[nf][1] = w.y;
            }
            unsigned afr[4][4];
#pragma unroll
            for (int mf = 0; mf < 4; mf++)
                ldsm_x4(afr[mf][0], afr[mf][1], afr[mf][2], afr[mf][3],
                        abase + ((arow0 + mf * 16) * ASTR + kk + acol0) * 2);
#pragma unroll
            for (int mf = 0; mf < 4; mf++)
#pragma unroll
                for (int nf = 0; nf < 4; nf++)
                    mma_f16(acc[mf][nf], afr[mf], bfr[nf], acc[mf][nf]);
        }
        __syncthreads();
    }

    const int seg = bn >> 8;
    const int segbase = bn & 255;
#pragma unroll
    for (int mf = 0; mf < 4; mf++) {
#pragma unroll
        for (int nf = 0; nf < 4; nf++) {
            int lcol = warp_n * 32 + nf * 8 + tig * 2;
            int cn   = bn + lcol;
            int scol = segbase + lcol;
            float b0 = g_bcat[cn], b1 = g_bcat[cn + 1];
#pragma unroll
            for (int half = 0; half < 2; half++) {
                int row = bm + warp_m * 64 + mf * 16 + gid + half * 8;
                if (row >= N_NODES) continue;
                float o0 = acc[mf][nf][half * 2 + 0] + b0;
                float o1 = acc[mf][nf][half * 2 + 1] + b1;
                if (seg == 0) {
                    *reinterpret_cast<float2*>(&g_qs[(size_t)row * 512 + scol]) =
                        make_float2(o0, o1);
                } else if (seg == 3) {
                    *reinterpret_cast<float2*>(&g_qs[(size_t)row * 512 + 256 + scol]) =
                        make_float2(o0, o1);
                } else {
                    __nv_bfloat162 h = __float22bfloat162_rn(make_float2(o0, o1));
                    __nv_bfloat16* dst = (seg == 1) ? g_k : g_v;
                    *reinterpret_cast<__nv_bfloat162*>(&dst[(size_t)row * 256 + scol]) = h;
                }
            }
        }
    }
}

// ---------------- CSR build (dst-grouped, runs on side stream) ----------------
// g_deg arrives zeroed: statically at first launch, self-cleaned by k_attn after.
__global__ void k_count(const int* __restrict__ ei) {
    int e = blockIdx.x * blockDim.x + threadIdx.x;
    if (e < E_EDGES) {
        int dst = ei[E_EDGES + e];
        if ((unsigned)dst < N_NODES) atomicAdd(&g_deg[dst], 1);
    }
}

__global__ __launch_bounds__(SCAN_B) void k_scan1() {
    int b = blockIdx.x, t = threadIdx.x;
    int i = b * SCAN_B + t;
    int v = (i < N_NODES) ? g_deg[i] : 0;
    int lane = t & 31, w = t >> 5;
    int x = v;
#pragma unroll
    for (int o = 1; o < 32; o <<= 1) {
        int y = __shfl_up_sync(0xFFFFFFFFu, x, o);
        if (lane >= o) x += y;
    }
    __shared__ int wsum[32];
    if (lane == 31) wsum[w] = x;
    __syncthreads();
    if (w == 0) {
        int s = wsum[lane];
#pragma unroll
        for (int o = 1; o < 32; o <<= 1) {
            int y = __shfl_up_sync(0xFFFFFFFFu, s, o);
            if (lane >= o) s += y;
        }
        wsum[lane] = s;
    }
    __syncthreads();
    int incl = x + (w > 0 ? wsum[w - 1] : 0);
    if (i < N_NODES) g_off[i] = incl - v;
    if (t == SCAN_B - 1) g_bsum[b] = incl;
}

__global__ void k_scan3() {
    __shared__ int pre;
    int b = blockIdx.x;
    if (threadIdx.x == 0) {
        int gb = (b << 8) / SCAN_B;
        int s = 0;
        for (int t = 0; t < gb; t++) s += g_bsum[t];
        pre = s;
    }
    __syncthreads();
    int i = (b << 8) + threadIdx.x;
    if (i < N_NODES) {
        int o = g_off[i] + pre;
        g_off[i] = o;
        g_cur[i] = o;
    }
}

__global__ void k_scatter(const int* __restrict__ ei) {
    int e = blockIdx.x * blockDim.x + threadIdx.x;
    if (e < E_EDGES) {
        int src = ei[e];
        int dst = ei[E_EDGES + e];
        if ((unsigned)src < N_NODES && (unsigned)dst < N_NODES) {
            int p = atomicAdd(&g_cur[dst], 1);
            if ((unsigned)p < E_EDGES) g_srcSorted[p] = src;
        }
    }
}

// ---------------- fused attention + skip + GELU + residual + LayerNorm ----------------
// WARP-PER-NODE, edge loop unrolled x4 (8 gathers in flight). Self-cleans g_deg.
__global__ __launch_bounds__(256) void k_attn(const float* __restrict__ x,
                                              const float* __restrict__ gamma,
                                              const float* __restrict__ beta,
                                              float* __restrict__ out) {
    const int wid  = threadIdx.x >> 5;
    const int lane = threadIdx.x & 31;
    const int i    = blockIdx.x * 8 + wid;
    if (i >= N_NODES) return;

    const int off = g_off[i];
    const int deg = g_deg[i];

    float q[8];
    {
        const float4* qp = reinterpret_cast<const float4*>(&g_qs[(size_t)i * 512 + lane * 8]);
        float4 q0 = __ldg(qp), q1 = __ldg(qp + 1);
        const float sc = 0.17677669529663689f;   // 1/sqrt(32)
        q[0] = q0.x * sc; q[1] = q0.y * sc; q[2] = q0.z * sc; q[3] = q0.w * sc;
        q[4] = q1.x * sc; q[5] = q1.y * sc; q[6] = q1.z * sc; q[7] = q1.w * sc;
    }

    float acc[8];
#pragma unroll
    for (int d = 0; d < 8; d++) acc[d] = 0.f;
    float denom = 0.f;

    int j = 0;
    for (; j + 4 <= deg; j += 4) {
        int s[4];
#pragma unroll
        for (int e = 0; e < 4; e++) s[e] = __ldg(&g_srcSorted[off + j + e]);
        uint4 kr[4], vr[4];
#pragma unroll
        for (int e = 0; e < 4; e++) {
            kr[e] = __ldg(reinterpret_cast<const uint4*>(&g_k[(size_t)s[e] * 256 + lane * 8]));
            vr[e] = __ldg(reinterpret_cast<const uint4*>(&g_v[(size_t)s[e] * 256 + lane * 8]));
        }
        float p[4];
#pragma unroll
        for (int e = 0; e < 4; e++) {
            unsigned u[4] = {kr[e].x, kr[e].y, kr[e].z, kr[e].w};
            float pe = 0.f;
#pragma unroll
            for (int t = 0; t < 4; t++) {
                float2 f = __bfloat1622float2(*reinterpret_cast<__nv_bfloat162*>(&u[t]));
                pe = fmaf(q[2 * t], f.x, fmaf(q[2 * t + 1], f.y, pe));
            }
            p[e] = pe;
        }
#pragma unroll
        for (int e = 0; e < 4; e++) {
            p[e] += __shfl_xor_sync(0xFFFFFFFFu, p[e], 1);
            p[e] += __shfl_xor_sync(0xFFFFFFFFu, p[e], 2);
        }
        float w[4];
#pragma unroll
        for (int e = 0; e < 4; e++) w[e] = __expf(p[e]);
#pragma unroll
        for (int e = 0; e < 4; e++) {
            denom += w[e];
            unsigned u[4] = {vr[e].x, vr[e].y, vr[e].z, vr[e].w};
#pragma unroll
            for (int t = 0; t < 4; t++) {
                float2 f = __bfloat1622float2(*reinterpret_cast<__nv_bfloat162*>(&u[t]));
                acc[2 * t]     = fmaf(w[e], f.x, acc[2 * t]);
                acc[2 * t + 1] = fmaf(w[e], f.y, acc[2 * t + 1]);
            }
        }
    }
    for (; j < deg; j++) {
        int s0 = __ldg(&g_srcSorted[off + j]);
        uint4 ka = __ldg(reinterpret_cast<const uint4*>(&g_k[(size_t)s0 * 256 + lane * 8]));
        uint4 va = __ldg(reinterpret_cast<const uint4*>(&g_v[(size_t)s0 * 256 + lane * 8]));
        unsigned ua[4] = {ka.x, ka.y, ka.z, ka.w};
        float p0 = 0.f;
#pragma unroll
        for (int t = 0; t < 4; t++) {
            float2 f = __bfloat1622float2(*reinterpret_cast<__nv_bfloat162*>(&ua[t]));
            p0 = fmaf(q[2 * t], f.x, fmaf(q[2 * t + 1], f.y, p0));
        }
        p0 += __shfl_xor_sync(0xFFFFFFFFu, p0, 1);
        p0 += __shfl_xor_sync(0xFFFFFFFFu, p0, 2);
        float w0 = __expf(p0);
        denom += w0;
        unsigned wa[4] = {va.x, va.y, va.z, va.w};
#pragma unroll
        for (int t = 0; t < 4; t++) {
            float2 f = __bfloat1622float2(*reinterpret_cast<__nv_bfloat162*>(&wa[t]));
            acc[2 * t]     = fmaf(w0, f.x, acc[2 * t]);
            acc[2 * t + 1] = fmaf(w0, f.y, acc[2 * t + 1]);
        }
    }

    const float inv_dn = (deg > 0) ? (1.f / denom) : 0.f;

    // self-clean degree for the next graph replay
    if (lane == 0) g_deg[i] = 0;

    float4 sk0, sk1, xv0, xv1;
    {
        const float4* sp = reinterpret_cast<const float4*>(&g_qs[(size_t)i * 512 + 256 + lane * 8]);
        sk0 = __ldg(sp); sk1 = __ldg(sp + 1);
        const float4* xp = reinterpret_cast<const float4*>(&x[(size_t)i * HID + lane * 8]);
        xv0 = __ldg(xp); xv1 = __ldg(xp + 1);
    }
    float skp[8] = {sk0.x, sk0.y, sk0.z, sk0.w, sk1.x, sk1.y, sk1.z, sk1.w};
    float xv[8]  = {xv0.x, xv0.y, xv0.z, xv0.w, xv1.x, xv1.y, xv1.z, xv1.w};

    float y[8];
    float s1 = 0.f, s2 = 0.f;
#pragma unroll
    for (int d = 0; d < 8; d++) {
        float o    = acc[d] * inv_dn + skp[d];
        float gelu = 0.5f * o * (1.f + erff(o * 0.70710678118654752f));
        float yy   = xv[d] + gelu;
        y[d] = yy;
        s1 += yy;
        s2 += yy * yy;
    }
#pragma unroll
    for (int o2 = 16; o2 > 0; o2 >>= 1) {
        s1 += __shfl_xor_sync(0xFFFFFFFFu, s1, o2);
        s2 += __shfl_xor_sync(0xFFFFFFFFu, s2, o2);
    }
    float mu  = s1 * (1.f / 256.f);
    float var = s2 * (1.f / 256.f) - mu * mu;
    float inv = rsqrtf(var + 1e-5f);

    const float4* gp = reinterpret_cast<const float4*>(&gamma[lane * 8]);
    const float4* bp = reinterpret_cast<const float4*>(&beta[lane * 8]);
    float4 g0 = __ldg(gp), g1 = __ldg(gp + 1);
    float4 b0 = __ldg(bp), b1 = __ldg(bp + 1);
    float gm[8] = {g0.x, g0.y, g0.z, g0.w, g1.x, g1.y, g1.z, g1.w};
    float bt[8] = {b0.x, b0.y, b0.z, b0.w, b1.x, b1.y, b1.z, b1.w};

    float4 o0, o1;
    o0.x = (y[0] - mu) * inv * gm[0] + bt[0];
    o0.y = (y[1] - mu) * inv * gm[1] + bt[1];
    o0.z = (y[2] - mu) * inv * gm[2] + bt[2];
    o0.w = (y[3] - mu) * inv * gm[3] + bt[3];
    o1.x = (y[4] - mu) * inv * gm[4] + bt[4];
    o1.y = (y[5] - mu) * inv * gm[5] + bt[5];
    o1.z = (y[6] - mu) * inv * gm[6] + bt[6];
    o1.w = (y[7] - mu) * inv * gm[7] + bt[7];
    float4* op = reinterpret_cast<float4*>(&out[(size_t)i * HID + lane * 8]);
    op[0] = o0;
    op[1] = o1;
}

// ---------------- launch: 3-way fork (gemm chain / cvtX / CSR), join at attn ----
extern "C" void kernel_launch(void* const* d_in, const int* in_sizes, int n_in,
                              void* d_out, int out_size) {
    const float* x     = (const float*)d_in[0];
    const int*   ei    = (const int*)d_in[1];     // int32 (JAX x64 disabled)
    const float* Wq    = (const float*)d_in[2];
    const float* bq    = (const float*)d_in[3];
    const float* Wk    = (const float*)d_in[4];
    const float* bk    = (const float*)d_in[5];
    const float* Wv    = (const float*)d_in[6];
    const float* bv    = (const float*)d_in[7];
    const float* Wsk   = (const float*)d_in[8];
    const float* bsk   = (const float*)d_in[9];
    const float* gamma = (const float*)d_in[10];
    const float* beta  = (const float*)d_in[11];
    float* out = (float*)d_out;

    static cudaStream_t s2 = nullptr, s3 = nullptr;
    static cudaEvent_t evFork = nullptr, evJoin = nullptr, evCvt = nullptr;
    if (s2 == nullptr) {
        cudaStreamCreateWithFlags(&s2, cudaStreamNonBlocking);
        cudaStreamCreateWithFlags(&s3, cudaStreamNonBlocking);
        cudaEventCreateWithFlags(&evFork, cudaEventDisableTiming);
        cudaEventCreateWithFlags(&evJoin, cudaEventDisableTiming);
        cudaEventCreateWithFlags(&evCvt, cudaEventDisableTiming);
    }

    cudaEventRecord(evFork, 0);
    cudaStreamWaitEvent(s2, evFork, 0);
    cudaStreamWaitEvent(s3, evFork, 0);

    k_packW<<<(128 * 16 * 32 + 255) / 256, 256>>>(Wq, Wk, Wv, Wsk, bq, bk, bv, bsk); // 1 (str0)
    k_cvtX<<<(N_NODES * 32 + 255) / 256, 256, 0, s3>>>(x);                            // 2 (s3)
    k_count<<<(E_EDGES + 255) / 256, 256, 0, s2>>>(ei);                               // 3 (s2)

    cudaEventRecord(evCvt, s3);
    cudaStreamWaitEvent(0, evCvt, 0);
    dim3 gg(NQKV / GBN, (N_NODES + GBM - 1) / GBM);
    k_gemm<<<gg, 256>>>();                                                            // 4 (str0, profiled)

    k_scan1<<<NBLK, SCAN_B, 0, s2>>>();                                               // 5 (s2)
    k_scan3<<<(N_NODES + 255) / 256, 256, 0, s2>>>();                                 // 6 (s2)
    k_scatter<<<(E_EDGES + 255) / 256, 256, 0, s2>>>(ei);                             // 7 (s2)

    cudaEventRecord(evJoin, s2);
    cudaStreamWaitEvent(0, evJoin, 0);
    k_attn<<<(N_NODES + 7) / 8, 256>>>(x, gamma, beta, out);                          // 8 (str0)
}